// round 5
// baseline (speedup 1.0000x reference)
#include <cuda_runtime.h>
#include <cstdint>
#include <math.h>

#define TOK 4096
#define DIM 1024
#define HID 1024
#define NE  16
#define SHH 2048

#define BMT 128       // CTA tile M
#define BNT 256       // CTA tile N
#define KC  32        // K chunk
#define SPAD 264      // B smem row stride in floats (== 8 mod 32: conflict-free)
#define ATILE 16384   // A tile bytes: 128 x 32 f32 (swizzled 128B rows)
#define BTILE (KC * SPAD * 4)            // 33792
#define STG   (ATILE + BTILE)            // 50176 per stage
#define SMEM_GEMM (2 * STG + 256)

// ---------------- scratch ----------------------------------------------------
__device__ int   g_cnt[NE];
__device__ int   g_list[NE * TOK];               // packed entry: token*2 + slot
__device__ float g_went[TOK * 2];                // routing weight per entry
__device__ float g_embr[(size_t)TOK * DIM];      // tf32-rounded embeddings
__device__ float g_xr[(size_t)TOK * DIM];        // tf32-rounded x
__device__ float g_ubuf[(size_t)TOK * 2 * HID];  // W1 pre-act, later expert outputs
__device__ float g_hbuf[(size_t)TOK * 2 * HID];  // SwiGLU hidden (tf32-rounded)
__device__ float g_zbuf[(size_t)TOK * SHH];      // shared-expert hidden (rounded)

// ---------------- helpers ------------------------------------------------------
__device__ __forceinline__ uint32_t smem_u32(const void* p) {
    uint32_t a;
    asm("{ .reg .u64 t; cvta.to.shared.u64 t, %1; cvt.u32.u64 %0, t; }"
        : "=r"(a) : "l"(p));
    return a;
}
__device__ __forceinline__ float rtf(float x) {
    uint32_t u;
    asm("cvt.rna.tf32.f32 %0, %1;" : "=r"(u) : "f"(x));
    return __uint_as_float(u);
}
__device__ __forceinline__ uint32_t swz(uint32_t o) {  // A tile XOR swizzle
    return o ^ (((o >> 7) & 7u) << 4);
}
__device__ __forceinline__ void cp16(uint32_t d, const void* s) {
    asm volatile("cp.async.cg.shared.global [%0], [%1], 16;" :: "r"(d), "l"(s));
}
__device__ __forceinline__ void cp16z(uint32_t d, const void* s, uint32_t n) {
    asm volatile("cp.async.cg.shared.global [%0], [%1], 16, %2;" :: "r"(d), "l"(s), "r"(n));
}
__device__ __forceinline__ void cp_commit() { asm volatile("cp.async.commit_group;"); }
__device__ __forceinline__ void cp_wait1()  { asm volatile("cp.async.wait_group 1;"); }
__device__ __forceinline__ void cp_wait0()  { asm volatile("cp.async.wait_group 0;"); }

__device__ __forceinline__ void ldsm4(uint32_t* r, uint32_t a) {
    asm volatile("ldmatrix.sync.aligned.m8n8.x4.shared.b16 {%0,%1,%2,%3}, [%4];"
                 : "=r"(r[0]), "=r"(r[1]), "=r"(r[2]), "=r"(r[3]) : "r"(a));
}
__device__ __forceinline__ void mma8(float* d, const uint32_t* a, uint32_t b0, uint32_t b1) {
    asm volatile("mma.sync.aligned.m16n8k8.row.col.f32.tf32.tf32.f32 "
                 "{%0,%1,%2,%3}, {%4,%5,%6,%7}, {%8,%9}, {%0,%1,%2,%3};"
                 : "+f"(d[0]), "+f"(d[1]), "+f"(d[2]), "+f"(d[3])
                 : "r"(a[0]), "r"(a[1]), "r"(a[2]), "r"(a[3]), "r"(b0), "r"(b1));
}

struct MMCtx {
    const float* a_src[4];   // per-thread A row pointers (gathered)
    uint32_t     a_dst[4];   // swizzled A dst offsets
    uint32_t     a_sz[4];    // 16 or 0
    const float* b_src;      // per-thread B base (row brow, col chunk)
    uint32_t     b_dst;      // B dst offset
    int          ldn;        // weight row stride (N)
};

__device__ __forceinline__ void mm_setup_a(MMCtx& cx, int tid) {
    int chunk = tid & 7, rb = tid >> 3;
#pragma unroll
    for (int i = 0; i < 4; i++) {
        int row = rb + 32 * i;
        cx.a_dst[i] = swz((uint32_t)row * 128u + (uint32_t)chunk * 16u);
    }
}
__device__ __forceinline__ void mm_issue(const MMCtx& cx, uint32_t sb, int buf, int c) {
    uint32_t ab = sb + buf * STG;
#pragma unroll
    for (int i = 0; i < 4; i++)
        cp16z(ab + cx.a_dst[i], cx.a_src[i] + c * KC, cx.a_sz[i]);
    uint32_t bb = ab + ATILE + cx.b_dst;
    const float* bs = cx.b_src + (size_t)c * KC * cx.ldn;
#pragma unroll
    for (int i = 0; i < 8; i++)
        cp16(bb + (uint32_t)i * 4u * (SPAD * 4u), bs + (size_t)i * 4 * cx.ldn);
    cp_commit();
}
__device__ __forceinline__ void mm_compute(uint32_t ab, const float* bs,
                                           float acc[4][8][4], int lane, int wm, int wn) {
#pragma unroll
    for (int ks = 0; ks < 4; ks++) {
        int k0 = ks * 8;
        uint32_t a[4][4];
#pragma unroll
        for (int mi = 0; mi < 4; mi++) {
            int row = wm * 64 + mi * 16 + (lane & 15);
            uint32_t o = (uint32_t)row * 128u + (uint32_t)(k0 + ((lane & 16) >> 2)) * 4u;
            ldsm4(a[mi], ab + swz(o));
        }
        const float* bp = bs + (size_t)(k0 + (lane & 3)) * SPAD + wn * 64 + (lane >> 2);
#pragma unroll
        for (int nj = 0; nj < 8; nj++) {
            uint32_t b0 = __float_as_uint(rtf(bp[nj * 8]));
            uint32_t b1 = __float_as_uint(rtf(bp[nj * 8 + 4 * SPAD]));
#pragma unroll
            for (int mi = 0; mi < 4; mi++)
                mma8(acc[mi][nj], a[mi], b0, b1);
        }
    }
}
__device__ __forceinline__ void mm_loop(const MMCtx& cx, uint32_t sb, const char* base,
                                        int K, float acc[4][8][4], int lane, int wm, int wn) {
    int NCH = K / KC;
    mm_issue(cx, sb, 0, 0);
    for (int c = 0; c < NCH; c++) {
        int b = c & 1;
        if (c + 1 < NCH) { mm_issue(cx, sb, b ^ 1, c + 1); cp_wait1(); }
        else             { cp_wait0(); }
        __syncthreads();
        mm_compute(sb + b * STG, (const float*)(base + b * STG + ATILE), acc, lane, wm, wn);
        __syncthreads();
    }
}

// ---------------- small kernels -------------------------------------------------
__global__ void k_zero() { if (threadIdx.x < NE) g_cnt[threadIdx.x] = 0; }

__global__ void k_round(const float* __restrict__ s, float* __restrict__ d, int n4) {
    int i = blockIdx.x * blockDim.x + threadIdx.x;
    if (i < n4) {
        float4 v = ((const float4*)s)[i];
        ((float4*)d)[i] = make_float4(rtf(v.x), rtf(v.y), rtf(v.z), rtf(v.w));
    }
}

__global__ void k_gate(const float* __restrict__ emb, const float* __restrict__ gw)
{
    int t = (blockIdx.x * blockDim.x + threadIdx.x) >> 5;
    int lane = threadIdx.x & 31;
    if (t >= TOK) return;
    const float* row = emb + (size_t)t * DIM;
    float xr[32];
#pragma unroll
    for (int i = 0; i < 32; i++) xr[i] = row[lane + 32 * i];
    float sc[NE];
#pragma unroll
    for (int e = 0; e < NE; e++) {
        const float* g = gw + e * DIM;
        float acc = 0.f;
#pragma unroll
        for (int i = 0; i < 32; i++) acc += xr[i] * g[lane + 32 * i];
#pragma unroll
        for (int o = 16; o > 0; o >>= 1) acc += __shfl_xor_sync(0xffffffffu, acc, o);
        sc[e] = acc;
    }
    if (lane == 0) {
        float m = sc[0];
#pragma unroll
        for (int e = 1; e < NE; e++) m = fmaxf(m, sc[e]);
        float s = 0.f;
#pragma unroll
        for (int e = 0; e < NE; e++) { sc[e] = expf(sc[e] - m); s += sc[e]; }
        float inv = 1.f / s;
        int i0 = 0;
#pragma unroll
        for (int e = 1; e < NE; e++) if (sc[e] > sc[i0]) i0 = e;
        int i1 = (i0 == 0) ? 1 : 0;
#pragma unroll
        for (int e = 0; e < NE; e++) if (e != i0 && sc[e] > sc[i1]) i1 = e;
        int p0 = atomicAdd(&g_cnt[i0], 1);
        g_list[i0 * TOK + p0] = t * 2;
        g_went[t * 2] = sc[i0] * inv;
        int p1 = atomicAdd(&g_cnt[i1], 1);
        g_list[i1 * TOK + p1] = t * 2 + 1;
        g_went[t * 2 + 1] = sc[i1] * inv;
    }
}

// ---------------- dense GEMM (shared expert) ------------------------------------
// EPI 0: C = acc + bias        EPI 1: C = rtf(silu(acc + bias))
template<int EPI>
__global__ void __launch_bounds__(256, 1) k_dense(
    const float* __restrict__ A, int lda,
    const float* __restrict__ Bw, int K, int ldn,
    const float* __restrict__ bias,
    float* __restrict__ C, int ldc)
{
    extern __shared__ char dsm[];
    char* base = (char*)(((uintptr_t)dsm + 127) & ~(uintptr_t)127);
    uint32_t sb = smem_u32(base);
    int tid = threadIdx.x, lane = tid & 31, w = tid >> 5;
    int wm = w >> 2, wn = w & 3;
    int r0 = blockIdx.y * BMT, c0 = blockIdx.x * BNT;

    MMCtx cx;
    mm_setup_a(cx, tid);
    {
        int chunk = tid & 7, rb = tid >> 3;
#pragma unroll
        for (int i = 0; i < 4; i++) {
            int row = rb + 32 * i;
            cx.a_src[i] = A + (size_t)(r0 + row) * lda + chunk * 4;
            cx.a_sz[i] = 16;
        }
        int c16 = tid & 63, brow = tid >> 6;
        cx.b_src = Bw + (size_t)brow * ldn + c0 + c16 * 4;
        cx.b_dst = (uint32_t)brow * (SPAD * 4u) + (uint32_t)c16 * 16u;
        cx.ldn = ldn;
    }
    float acc[4][8][4] = {};
    mm_loop(cx, sb, base, K, acc, lane, wm, wn);

    int g = lane >> 2, t4 = lane & 3;
#pragma unroll
    for (int mi = 0; mi < 4; mi++)
#pragma unroll
        for (int h = 0; h < 2; h++) {
            int row = r0 + wm * 64 + mi * 16 + g + h * 8;
            float* cp = C + (size_t)row * ldc;
#pragma unroll
            for (int nj = 0; nj < 8; nj++) {
                int col = c0 + wn * 64 + nj * 8 + 2 * t4;
                float v0 = acc[mi][nj][h * 2 + 0] + bias[col];
                float v1 = acc[mi][nj][h * 2 + 1] + bias[col + 1];
                if (EPI == 1) {
                    v0 = rtf(v0 / (1.f + __expf(-v0)));
                    v1 = rtf(v1 / (1.f + __expf(-v1)));
                }
                *(float2*)(cp + col) = make_float2(v0, v1);
            }
        }
}

// ---------------- routed GEMM ----------------------------------------------------
// GM 0: gather token rows (ent>>1) from p0 (e<2) else p1;  GM 1: gather hbuf rows (ent)
// EPI 0: C[ent] = acc + bias   EPI 3: C[ent] = rtf(silu(ubuf[ent]) * (acc + bias))
template<int GM, int EPI>
__global__ void __launch_bounds__(256, 1) k_moe(
    const float* __restrict__ p0, const float* __restrict__ p1,
    const float* __restrict__ Bw_all, int K, int ldn,
    const float* __restrict__ bias_all,
    float* __restrict__ C, int ldc)
{
    int e = blockIdx.z;
    int cnt = g_cnt[e];
    int r0 = blockIdx.y * BMT;
    if (r0 >= cnt) return;
    int c0 = blockIdx.x * BNT;

    extern __shared__ char dsm[];
    __shared__ int rs[BMT];
    char* base = (char*)(((uintptr_t)dsm + 127) & ~(uintptr_t)127);
    uint32_t sb = smem_u32(base);
    int tid = threadIdx.x, lane = tid & 31, w = tid >> 5;
    int wm = w >> 2, wn = w & 3;

    if (tid < BMT) rs[tid] = (r0 + tid < cnt) ? g_list[e * TOK + r0 + tid] : -1;
    __syncthreads();

    MMCtx cx;
    mm_setup_a(cx, tid);
    {
        int chunk = tid & 7, rb = tid >> 3;
        const float* abase = (GM == 0) ? ((e < 2) ? p0 : p1) : p0;
        const int lda = (GM == 0) ? DIM : HID;
#pragma unroll
        for (int i = 0; i < 4; i++) {
            int row = rb + 32 * i;
            int ent = rs[row];
            bool v = (ent >= 0);
            int arow = (GM == 0) ? (ent >> 1) : ent;
            cx.a_src[i] = v ? abase + (size_t)arow * lda + chunk * 4 : abase;
            cx.a_sz[i] = v ? 16 : 0;
        }
        int c16 = tid & 63, brow = tid >> 6;
        cx.b_src = Bw_all + (size_t)e * K * ldn + (size_t)brow * ldn + c0 + c16 * 4;
        cx.b_dst = (uint32_t)brow * (SPAD * 4u) + (uint32_t)c16 * 16u;
        cx.ldn = ldn;
    }
    float acc[4][8][4] = {};
    mm_loop(cx, sb, base, K, acc, lane, wm, wn);

    const float* bias = bias_all + (size_t)e * ldn;
    int g = lane >> 2, t4 = lane & 3;
#pragma unroll
    for (int mi = 0; mi < 4; mi++)
#pragma unroll
        for (int h = 0; h < 2; h++) {
            int lr = wm * 64 + mi * 16 + g + h * 8;
            int ent = rs[lr];
            if (ent < 0) continue;
            float* cp = C + (size_t)ent * ldc;
            const float* up = g_ubuf + (size_t)ent * HID;
#pragma unroll
            for (int nj = 0; nj < 8; nj++) {
                int col = c0 + wn * 64 + nj * 8 + 2 * t4;
                float v0 = acc[mi][nj][h * 2 + 0] + bias[col];
                float v1 = acc[mi][nj][h * 2 + 1] + bias[col + 1];
                if (EPI == 3) {
                    float2 u = *(const float2*)(up + col);
                    v0 = rtf((u.x / (1.f + __expf(-u.x))) * v0);
                    v1 = rtf((u.y / (1.f + __expf(-u.y))) * v1);
                }
                *(float2*)(cp + col) = make_float2(v0, v1);
            }
        }
}

// ---------------- final combine: out[t] += w0*o[2t] + w1*o[2t+1] ------------------
__global__ void k_comb(float* __restrict__ out) {
    int t = blockIdx.x;
    int d = threadIdx.x * 4;
    float w0 = g_went[t * 2], w1 = g_went[t * 2 + 1];
    float4 a = *(const float4*)(g_ubuf + (size_t)(t * 2) * DIM + d);
    float4 b = *(const float4*)(g_ubuf + (size_t)(t * 2 + 1) * DIM + d);
    float4 z = *(float4*)(out + (size_t)t * DIM + d);
    z.x += w0 * a.x + w1 * b.x;
    z.y += w0 * a.y + w1 * b.y;
    z.z += w0 * a.z + w1 * b.z;
    z.w += w0 * a.w + w1 * b.w;
    *(float4*)(out + (size_t)t * DIM + d) = z;
}

// ---------------- launcher ---------------------------------------------------------
extern "C" void kernel_launch(void* const* d_in, const int* in_sizes, int n_in,
                              void* d_out, int out_size)
{
    const float* emb = (const float*)d_in[0];
    const float* x   = (const float*)d_in[1];
    const float* gw  = (const float*)d_in[2];
    const float* W1  = (const float*)d_in[3];
    const float* B1  = (const float*)d_in[4];
    const float* W2  = (const float*)d_in[5];
    const float* B2  = (const float*)d_in[6];
    const float* W3  = (const float*)d_in[7];
    const float* B3  = (const float*)d_in[8];
    const float* sW1 = (const float*)d_in[9];
    const float* sB1 = (const float*)d_in[10];
    const float* sW2 = (const float*)d_in[11];
    const float* sB2 = (const float*)d_in[12];
    float* out = (float*)d_out;

    cudaFuncSetAttribute(k_dense<0>, cudaFuncAttributeMaxDynamicSharedMemorySize, SMEM_GEMM);
    cudaFuncSetAttribute(k_dense<1>, cudaFuncAttributeMaxDynamicSharedMemorySize, SMEM_GEMM);
    cudaFuncSetAttribute(k_moe<0,0>, cudaFuncAttributeMaxDynamicSharedMemorySize, SMEM_GEMM);
    cudaFuncSetAttribute(k_moe<0,3>, cudaFuncAttributeMaxDynamicSharedMemorySize, SMEM_GEMM);
    cudaFuncSetAttribute(k_moe<1,0>, cudaFuncAttributeMaxDynamicSharedMemorySize, SMEM_GEMM);

    float *embr, *xr, *ubuf, *hbuf, *zbuf;
    cudaGetSymbolAddress((void**)&embr, g_embr);
    cudaGetSymbolAddress((void**)&xr,   g_xr);
    cudaGetSymbolAddress((void**)&ubuf, g_ubuf);
    cudaGetSymbolAddress((void**)&hbuf, g_hbuf);
    cudaGetSymbolAddress((void**)&zbuf, g_zbuf);

    k_zero<<<1, 32>>>();
    k_gate<<<TOK / 4, 128>>>(emb, gw);

    int n4a = TOK * DIM / 4;
    k_round<<<(n4a + 255) / 256, 256>>>(emb, embr, n4a);
    k_round<<<(n4a + 255) / 256, 256>>>(x,   xr,   n4a);

    // shared expert
    k_dense<1><<<dim3(SHH / BNT, TOK / BMT), 256, SMEM_GEMM>>>(embr, DIM, sW1, DIM, SHH, sB1, zbuf, SHH);
    k_dense<0><<<dim3(DIM / BNT, TOK / BMT), 256, SMEM_GEMM>>>(zbuf, SHH, sW2, SHH, DIM, sB2, out, DIM);

    // routed experts: u = W1 pre-act; h = rtf(silu(u) * (W3 pre-act)); o = h @ W2 + B2
    k_moe<0,0><<<dim3(HID / BNT, TOK / BMT, NE), 256, SMEM_GEMM>>>(xr, embr, W1, DIM, HID, B1, ubuf, HID);
    k_moe<0,3><<<dim3(HID / BNT, TOK / BMT, NE), 256, SMEM_GEMM>>>(xr, embr, W3, DIM, HID, B3, hbuf, HID);
    k_moe<1,0><<<dim3(DIM / BNT, TOK / BMT, NE), 256, SMEM_GEMM>>>(hbuf, hbuf, W2, HID, DIM, B2, ubuf, DIM);
    k_comb<<<TOK, 256>>>(out);

    (void)in_sizes; (void)n_in; (void)out_size;
}

// round 6
// speedup vs baseline: 1.0984x; 1.0984x over previous
#include <cuda_runtime.h>
#include <cstdint>
#include <math.h>

#define TOK 4096
#define DIM 1024
#define HID 1024
#define NE  16
#define SHH 2048

#define BMT 128       // CTA tile M
#define BNT 128       // CTA tile N
#define KC  32        // K chunk
#define SPB 136       // B smem row stride in floats (== 8 mod 32: conflict-free)
#define ATILE 16384   // A tile: 128 rows x 128B (swizzled)
#define BTILE (KC * SPB * 4)      // 17408
#define STG   (ATILE + BTILE)     // 33792 per stage
#define SMEM_GEMM (2 * STG + 256) // 67840 -> 2 CTAs/SM

// ---------------- scratch ----------------------------------------------------
__device__ int   g_cnt[NE];
__device__ int   g_list[NE * TOK];               // packed entry: token*2 + slot
__device__ float g_went[TOK * 2];                // routing weight per entry
__device__ float g_embr[(size_t)TOK * DIM];      // tf32-rounded embeddings
__device__ float g_xr[(size_t)TOK * DIM];        // tf32-rounded x
__device__ float g_ubuf[(size_t)TOK * 2 * HID];  // W1 pre-act, later expert outputs
__device__ float g_hbuf[(size_t)TOK * 2 * HID];  // SwiGLU hidden (tf32-rounded)
__device__ float g_zbuf[(size_t)TOK * SHH];      // shared-expert hidden (rounded)

// ---------------- helpers ------------------------------------------------------
__device__ __forceinline__ uint32_t smem_u32(const void* p) {
    uint32_t a;
    asm("{ .reg .u64 t; cvta.to.shared.u64 t, %1; cvt.u32.u64 %0, t; }"
        : "=r"(a) : "l"(p));
    return a;
}
__device__ __forceinline__ float rtf(float x) {
    uint32_t u;
    asm("cvt.rna.tf32.f32 %0, %1;" : "=r"(u) : "f"(x));
    return __uint_as_float(u);
}
__device__ __forceinline__ uint32_t swz(uint32_t o) {  // A tile XOR swizzle
    return o ^ (((o >> 7) & 7u) << 4);
}
__device__ __forceinline__ void cp16(uint32_t d, const void* s) {
    asm volatile("cp.async.cg.shared.global [%0], [%1], 16;" :: "r"(d), "l"(s));
}
__device__ __forceinline__ void cp16z(uint32_t d, const void* s, uint32_t n) {
    asm volatile("cp.async.cg.shared.global [%0], [%1], 16, %2;" :: "r"(d), "l"(s), "r"(n));
}
__device__ __forceinline__ void cp_commit() { asm volatile("cp.async.commit_group;"); }
__device__ __forceinline__ void cp_wait1()  { asm volatile("cp.async.wait_group 1;"); }
__device__ __forceinline__ void cp_wait0()  { asm volatile("cp.async.wait_group 0;"); }

__device__ __forceinline__ void ldsm4(uint32_t* r, uint32_t a) {
    asm volatile("ldmatrix.sync.aligned.m8n8.x4.shared.b16 {%0,%1,%2,%3}, [%4];"
                 : "=r"(r[0]), "=r"(r[1]), "=r"(r[2]), "=r"(r[3]) : "r"(a));
}
__device__ __forceinline__ void mma8(float* d, const uint32_t* a, uint32_t b0, uint32_t b1) {
    asm volatile("mma.sync.aligned.m16n8k8.row.col.f32.tf32.tf32.f32 "
                 "{%0,%1,%2,%3}, {%4,%5,%6,%7}, {%8,%9}, {%0,%1,%2,%3};"
                 : "+f"(d[0]), "+f"(d[1]), "+f"(d[2]), "+f"(d[3])
                 : "r"(a[0]), "r"(a[1]), "r"(a[2]), "r"(a[3]), "r"(b0), "r"(b1));
}

struct MMCtx {
    const float* a_src[4];   // per-thread A row pointers (gathered)
    uint32_t     a_dst[4];   // swizzled A dst offsets
    uint32_t     a_sz[4];    // 16 or 0
    const float* b_src;      // per-thread B gmem base
    uint32_t     b_dst;      // per-thread B smem dst offset
    int          ldn;        // weight row stride (N)
};

__device__ __forceinline__ void mm_setup_a(MMCtx& cx, int tid) {
    int chunk = tid & 7, rb = tid >> 3;
#pragma unroll
    for (int i = 0; i < 4; i++) {
        int row = rb + 32 * i;
        cx.a_dst[i] = swz((uint32_t)row * 128u + (uint32_t)chunk * 16u);
    }
}
// B tile: [KC rows][BNT floats] at stride SPB floats; thread covers rows bk+8j, 16B col chunk bn.
__device__ __forceinline__ void mm_issue(const MMCtx& cx, uint32_t sb, int buf, int c) {
    uint32_t ab = sb + buf * STG;
#pragma unroll
    for (int i = 0; i < 4; i++)
        cp16z(ab + cx.a_dst[i], cx.a_src[i] + c * KC, cx.a_sz[i]);
    uint32_t bb = ab + ATILE + cx.b_dst;
    const float* bs = cx.b_src + (size_t)c * KC * cx.ldn;
#pragma unroll
    for (int j = 0; j < 4; j++)
        cp16(bb + (uint32_t)j * 8u * (SPB * 4u), bs + (size_t)j * 8 * cx.ldn);
    cp_commit();
}
__device__ __forceinline__ void mm_compute(uint32_t ab, const float* bs,
                                           float acc[2][8][4], int lane, int wm, int wn) {
#pragma unroll
    for (int ks = 0; ks < 4; ks++) {
        int k0 = ks * 8;
        uint32_t a[2][4];
#pragma unroll
        for (int mi = 0; mi < 2; mi++) {
            int row = wm * 32 + mi * 16 + (lane & 15);
            uint32_t o = (uint32_t)row * 128u + (uint32_t)(k0 + ((lane & 16) >> 2)) * 4u;
            ldsm4(a[mi], ab + swz(o));
        }
        const float* bp = bs + (size_t)(k0 + (lane & 3)) * SPB + wn * 64 + (lane >> 2);
#pragma unroll
        for (int nj = 0; nj < 8; nj++) {
            uint32_t b0 = __float_as_uint(rtf(bp[nj * 8]));
            uint32_t b1 = __float_as_uint(rtf(bp[nj * 8 + 4 * SPB]));
            mma8(acc[0][nj], a[0], b0, b1);
            mma8(acc[1][nj], a[1], b0, b1);
        }
    }
}
__device__ __forceinline__ void mm_loop(const MMCtx& cx, uint32_t sb, const char* base,
                                        int K, float acc[2][8][4], int lane, int wm, int wn) {
    int NCH = K / KC;
    mm_issue(cx, sb, 0, 0);
    for (int c = 0; c < NCH; c++) {
        int b = c & 1;
        if (c + 1 < NCH) { mm_issue(cx, sb, b ^ 1, c + 1); cp_wait1(); }
        else             { cp_wait0(); }
        __syncthreads();
        mm_compute(sb + b * STG, (const float*)(base + b * STG + ATILE), acc, lane, wm, wn);
        __syncthreads();
    }
}

// ---------------- small kernels -------------------------------------------------
__global__ void k_zero() { if (threadIdx.x < NE) g_cnt[threadIdx.x] = 0; }

__global__ void k_round(const float* __restrict__ s, float* __restrict__ d, int n4) {
    int i = blockIdx.x * blockDim.x + threadIdx.x;
    if (i < n4) {
        float4 v = ((const float4*)s)[i];
        ((float4*)d)[i] = make_float4(rtf(v.x), rtf(v.y), rtf(v.z), rtf(v.w));
    }
}

__global__ void k_gate(const float* __restrict__ emb, const float* __restrict__ gw)
{
    int t = (blockIdx.x * blockDim.x + threadIdx.x) >> 5;
    int lane = threadIdx.x & 31;
    if (t >= TOK) return;
    const float* row = emb + (size_t)t * DIM;
    float xr[32];
#pragma unroll
    for (int i = 0; i < 32; i++) xr[i] = row[lane + 32 * i];
    float sc[NE];
#pragma unroll
    for (int e = 0; e < NE; e++) {
        const float* g = gw + e * DIM;
        float acc = 0.f;
#pragma unroll
        for (int i = 0; i < 32; i++) acc += xr[i] * g[lane + 32 * i];
#pragma unroll
        for (int o = 16; o > 0; o >>= 1) acc += __shfl_xor_sync(0xffffffffu, acc, o);
        sc[e] = acc;
    }
    if (lane == 0) {
        float m = sc[0];
#pragma unroll
        for (int e = 1; e < NE; e++) m = fmaxf(m, sc[e]);
        float s = 0.f;
#pragma unroll
        for (int e = 0; e < NE; e++) { sc[e] = expf(sc[e] - m); s += sc[e]; }
        float inv = 1.f / s;
        int i0 = 0;
#pragma unroll
        for (int e = 1; e < NE; e++) if (sc[e] > sc[i0]) i0 = e;
        int i1 = (i0 == 0) ? 1 : 0;
#pragma unroll
        for (int e = 0; e < NE; e++) if (e != i0 && sc[e] > sc[i1]) i1 = e;
        int p0 = atomicAdd(&g_cnt[i0], 1);
        g_list[i0 * TOK + p0] = t * 2;
        g_went[t * 2] = sc[i0] * inv;
        int p1 = atomicAdd(&g_cnt[i1], 1);
        g_list[i1 * TOK + p1] = t * 2 + 1;
        g_went[t * 2 + 1] = sc[i1] * inv;
    }
}

// ---------------- dense GEMM (shared expert) ------------------------------------
// EPI 0: C = acc + bias        EPI 1: C = rtf(silu(acc + bias))
template<int EPI>
__global__ void __launch_bounds__(256, 2) k_dense(
    const float* __restrict__ A, int lda,
    const float* __restrict__ Bw, int K, int ldn,
    const float* __restrict__ bias,
    float* __restrict__ C, int ldc)
{
    extern __shared__ char dsm[];
    char* base = (char*)(((uintptr_t)dsm + 127) & ~(uintptr_t)127);
    uint32_t sb = smem_u32(base);
    int tid = threadIdx.x, lane = tid & 31, w = tid >> 5;
    int wm = w & 3, wn = w >> 2;
    int r0 = blockIdx.y * BMT, c0 = blockIdx.x * BNT;

    MMCtx cx;
    mm_setup_a(cx, tid);
    {
        int chunk = tid & 7, rb = tid >> 3;
#pragma unroll
        for (int i = 0; i < 4; i++) {
            int row = rb + 32 * i;
            cx.a_src[i] = A + (size_t)(r0 + row) * lda + chunk * 4;
            cx.a_sz[i] = 16;
        }
        int bn = tid & 31, bk = tid >> 5;           // bn: 16B col chunk, bk: base row
        cx.b_src = Bw + (size_t)bk * ldn + c0 + bn * 4;
        cx.b_dst = (uint32_t)bk * (SPB * 4u) + (uint32_t)bn * 16u;
        cx.ldn = ldn;
    }
    float acc[2][8][4] = {};
    mm_loop(cx, sb, base, K, acc, lane, wm, wn);

    int g = lane >> 2, t4 = lane & 3;
#pragma unroll
    for (int mi = 0; mi < 2; mi++)
#pragma unroll
        for (int h = 0; h < 2; h++) {
            int row = r0 + wm * 32 + mi * 16 + g + h * 8;
            float* cp = C + (size_t)row * ldc;
#pragma unroll
            for (int nj = 0; nj < 8; nj++) {
                int col = c0 + wn * 64 + nj * 8 + 2 * t4;
                float v0 = acc[mi][nj][h * 2 + 0] + bias[col];
                float v1 = acc[mi][nj][h * 2 + 1] + bias[col + 1];
                if (EPI == 1) {
                    v0 = rtf(v0 / (1.f + __expf(-v0)));
                    v1 = rtf(v1 / (1.f + __expf(-v1)));
                }
                *(float2*)(cp + col) = make_float2(v0, v1);
            }
        }
}

// ---------------- routed GEMM ----------------------------------------------------
// GM 0: gather token rows (ent>>1) from p0 (e<2) else p1;  GM 1: gather hbuf rows (ent)
// EPI 0: C[ent] = acc + bias   EPI 3: C[ent] = rtf(silu(ubuf[ent]) * (acc + bias))
template<int GM, int EPI>
__global__ void __launch_bounds__(256, 2) k_moe(
    const float* __restrict__ p0, const float* __restrict__ p1,
    const float* __restrict__ Bw_all, int K, int ldn,
    const float* __restrict__ bias_all,
    float* __restrict__ C, int ldc)
{
    int e = blockIdx.z;
    int cnt = g_cnt[e];
    int r0 = blockIdx.y * BMT;
    if (r0 >= cnt) return;
    int c0 = blockIdx.x * BNT;

    extern __shared__ char dsm[];
    __shared__ int rs[BMT];
    char* base = (char*)(((uintptr_t)dsm + 127) & ~(uintptr_t)127);
    uint32_t sb = smem_u32(base);
    int tid = threadIdx.x, lane = tid & 31, w = tid >> 5;
    int wm = w & 3, wn = w >> 2;

    if (tid < BMT) rs[tid] = (r0 + tid < cnt) ? g_list[e * TOK + r0 + tid] : -1;
    __syncthreads();

    MMCtx cx;
    mm_setup_a(cx, tid);
    {
        int chunk = tid & 7, rb = tid >> 3;
        const float* abase = (GM == 0) ? ((e < 2) ? p0 : p1) : p0;
        const int lda = DIM;   // DIM == HID == 1024 for both gather modes
#pragma unroll
        for (int i = 0; i < 4; i++) {
            int row = rb + 32 * i;
            int ent = rs[row];
            bool v = (ent >= 0);
            int arow = (GM == 0) ? (ent >> 1) : ent;
            cx.a_src[i] = v ? abase + (size_t)arow * lda + chunk * 4 : abase;
            cx.a_sz[i] = v ? 16 : 0;
        }
        int bn = tid & 31, bk = tid >> 5;
        cx.b_src = Bw_all + (size_t)e * K * ldn + (size_t)bk * ldn + c0 + bn * 4;
        cx.b_dst = (uint32_t)bk * (SPB * 4u) + (uint32_t)bn * 16u;
        cx.ldn = ldn;
    }
    float acc[2][8][4] = {};
    mm_loop(cx, sb, base, K, acc, lane, wm, wn);

    const float* bias = bias_all + (size_t)e * ldn;
    int g = lane >> 2, t4 = lane & 3;
#pragma unroll
    for (int mi = 0; mi < 2; mi++)
#pragma unroll
        for (int h = 0; h < 2; h++) {
            int lr = wm * 32 + mi * 16 + g + h * 8;
            int ent = rs[lr];
            if (ent < 0) continue;
            float* cp = C + (size_t)ent * ldc;
            const float* up = g_ubuf + (size_t)ent * HID;
#pragma unroll
            for (int nj = 0; nj < 8; nj++) {
                int col = c0 + wn * 64 + nj * 8 + 2 * t4;
                float v0 = acc[mi][nj][h * 2 + 0] + bias[col];
                float v1 = acc[mi][nj][h * 2 + 1] + bias[col + 1];
                if (EPI == 3) {
                    float2 u = *(const float2*)(up + col);
                    v0 = rtf((u.x / (1.f + __expf(-u.x))) * v0);
                    v1 = rtf((u.y / (1.f + __expf(-u.y))) * v1);
                }
                *(float2*)(cp + col) = make_float2(v0, v1);
            }
        }
}

// ---------------- final combine: out[t] += w0*o[2t] + w1*o[2t+1] ------------------
__global__ void k_comb(float* __restrict__ out) {
    int t = blockIdx.x;
    int d = threadIdx.x * 4;
    float w0 = g_went[t * 2], w1 = g_went[t * 2 + 1];
    float4 a = *(const float4*)(g_ubuf + (size_t)(t * 2) * DIM + d);
    float4 b = *(const float4*)(g_ubuf + (size_t)(t * 2 + 1) * DIM + d);
    float4 z = *(float4*)(out + (size_t)t * DIM + d);
    z.x += w0 * a.x + w1 * b.x;
    z.y += w0 * a.y + w1 * b.y;
    z.z += w0 * a.z + w1 * b.z;
    z.w += w0 * a.w + w1 * b.w;
    *(float4*)(out + (size_t)t * DIM + d) = z;
}

// ---------------- launcher ---------------------------------------------------------
extern "C" void kernel_launch(void* const* d_in, const int* in_sizes, int n_in,
                              void* d_out, int out_size)
{
    const float* emb = (const float*)d_in[0];
    const float* x   = (const float*)d_in[1];
    const float* gw  = (const float*)d_in[2];
    const float* W1  = (const float*)d_in[3];
    const float* B1  = (const float*)d_in[4];
    const float* W2  = (const float*)d_in[5];
    const float* B2  = (const float*)d_in[6];
    const float* W3  = (const float*)d_in[7];
    const float* B3  = (const float*)d_in[8];
    const float* sW1 = (const float*)d_in[9];
    const float* sB1 = (const float*)d_in[10];
    const float* sW2 = (const float*)d_in[11];
    const float* sB2 = (const float*)d_in[12];
    float* out = (float*)d_out;

    cudaFuncSetAttribute(k_dense<0>, cudaFuncAttributeMaxDynamicSharedMemorySize, SMEM_GEMM);
    cudaFuncSetAttribute(k_dense<1>, cudaFuncAttributeMaxDynamicSharedMemorySize, SMEM_GEMM);
    cudaFuncSetAttribute(k_moe<0,0>, cudaFuncAttributeMaxDynamicSharedMemorySize, SMEM_GEMM);
    cudaFuncSetAttribute(k_moe<0,3>, cudaFuncAttributeMaxDynamicSharedMemorySize, SMEM_GEMM);
    cudaFuncSetAttribute(k_moe<1,0>, cudaFuncAttributeMaxDynamicSharedMemorySize, SMEM_GEMM);

    float *embr, *xr, *ubuf, *hbuf, *zbuf;
    cudaGetSymbolAddress((void**)&embr, g_embr);
    cudaGetSymbolAddress((void**)&xr,   g_xr);
    cudaGetSymbolAddress((void**)&ubuf, g_ubuf);
    cudaGetSymbolAddress((void**)&hbuf, g_hbuf);
    cudaGetSymbolAddress((void**)&zbuf, g_zbuf);

    k_zero<<<1, 32>>>();
    k_gate<<<TOK / 4, 128>>>(emb, gw);

    int n4a = TOK * DIM / 4;
    k_round<<<(n4a + 255) / 256, 256>>>(emb, embr, n4a);
    k_round<<<(n4a + 255) / 256, 256>>>(x,   xr,   n4a);

    // shared expert
    k_dense<1><<<dim3(SHH / BNT, TOK / BMT), 256, SMEM_GEMM>>>(embr, DIM, sW1, DIM, SHH, sB1, zbuf, SHH);
    k_dense<0><<<dim3(DIM / BNT, TOK / BMT), 256, SMEM_GEMM>>>(zbuf, SHH, sW2, SHH, DIM, sB2, out, DIM);

    // routed experts: u = W1 pre-act; h = rtf(silu(u) * (W3 pre-act)); o = h @ W2 + B2
    k_moe<0,0><<<dim3(HID / BNT, TOK / BMT, NE), 256, SMEM_GEMM>>>(xr, embr, W1, DIM, HID, B1, ubuf, HID);
    k_moe<0,3><<<dim3(HID / BNT, TOK / BMT, NE), 256, SMEM_GEMM>>>(xr, embr, W3, DIM, HID, B3, hbuf, HID);
    k_moe<1,0><<<dim3(DIM / BNT, TOK / BMT, NE), 256, SMEM_GEMM>>>(hbuf, hbuf, W2, HID, DIM, B2, ubuf, DIM);
    k_comb<<<TOK, 256>>>(out);

    (void)in_sizes; (void)n_in; (void)out_size;
}

// round 7
// speedup vs baseline: 1.1166x; 1.0166x over previous
#include <cuda_runtime.h>
#include <cstdint>
#include <math.h>

#define TOK 4096
#define DIM 1024
#define HID 1024
#define NE  16
#define SHH 2048

#define BMT 128       // CTA tile M
#define BNT 128       // CTA tile N
#define KC  32        // K chunk
#define TLB 16384     // one operand tile: 128 rows x 128B (swizzled)
#define STG (2 * TLB) // A+B per stage
#define NSTG 3
#define SMEM_GEMM (NSTG * STG + 256)   // 98560 -> 2 CTAs/SM

// ---------------- scratch ----------------------------------------------------
__device__ int   g_cnt[NE];
__device__ int   g_list[NE * TOK];               // packed entry: token*2 + slot
__device__ float g_went[TOK * 2];                // routing weight per entry
__device__ float g_embr[(size_t)TOK * DIM];      // tf32-rounded embeddings
__device__ float g_xr[(size_t)TOK * DIM];        // tf32-rounded x
__device__ float g_ubuf[(size_t)TOK * 2 * HID];  // W1 pre-act, later expert outputs
__device__ float g_hbuf[(size_t)TOK * 2 * HID];  // SwiGLU hidden (tf32-rounded)
__device__ float g_zbuf[(size_t)TOK * SHH];      // shared-expert hidden (rounded)
__device__ float g_tw1[(size_t)NE * DIM * HID];  // W1^T  [e][h][d] (tf32)
__device__ float g_tw3[(size_t)NE * DIM * HID];  // W3^T  [e][h][d]
__device__ float g_tw2[(size_t)NE * DIM * HID];  // W2^T  [e][d][h]
__device__ float g_tsw1[(size_t)SHH * DIM];      // sW1^T [h][d]
__device__ float g_tsw2[(size_t)DIM * SHH];      // sW2^T [d][h]

// ---------------- helpers ------------------------------------------------------
__device__ __forceinline__ uint32_t smem_u32(const void* p) {
    uint32_t a;
    asm("{ .reg .u64 t; cvta.to.shared.u64 t, %1; cvt.u32.u64 %0, t; }"
        : "=r"(a) : "l"(p));
    return a;
}
__device__ __forceinline__ float rtf(float x) {
    uint32_t u;
    asm("cvt.rna.tf32.f32 %0, %1;" : "=r"(u) : "f"(x));
    return __uint_as_float(u);
}
__device__ __forceinline__ uint32_t swz(uint32_t o) {  // XOR bits[4:6] ^= row[0:2]
    return o ^ (((o >> 7) & 7u) << 4);
}
__device__ __forceinline__ void cp16(uint32_t d, const void* s) {
    asm volatile("cp.async.cg.shared.global [%0], [%1], 16;" :: "r"(d), "l"(s));
}
__device__ __forceinline__ void cp16z(uint32_t d, const void* s, uint32_t n) {
    asm volatile("cp.async.cg.shared.global [%0], [%1], 16, %2;" :: "r"(d), "l"(s), "r"(n));
}
__device__ __forceinline__ void cp_commit() { asm volatile("cp.async.commit_group;"); }
__device__ __forceinline__ void cp_wait1()  { asm volatile("cp.async.wait_group 1;"); }
__device__ __forceinline__ void cp_wait0()  { asm volatile("cp.async.wait_group 0;"); }

__device__ __forceinline__ void ldsm4(uint32_t* r, uint32_t a) {
    asm volatile("ldmatrix.sync.aligned.m8n8.x4.shared.b16 {%0,%1,%2,%3}, [%4];"
                 : "=r"(r[0]), "=r"(r[1]), "=r"(r[2]), "=r"(r[3]) : "r"(a));
}
__device__ __forceinline__ void mma8(float* d, const uint32_t* a, uint32_t b0, uint32_t b1) {
    asm volatile("mma.sync.aligned.m16n8k8.row.col.f32.tf32.tf32.f32 "
                 "{%0,%1,%2,%3}, {%4,%5,%6,%7}, {%8,%9}, {%0,%1,%2,%3};"
                 : "+f"(d[0]), "+f"(d[1]), "+f"(d[2]), "+f"(d[3])
                 : "r"(a[0]), "r"(a[1]), "r"(a[2]), "r"(a[3]), "r"(b0), "r"(b1));
}

struct MMCtx {
    const float* a_src[4];   // per-thread A row pointers (gathered)
    const float* b_src[4];   // per-thread B row pointers (transposed weights)
    uint32_t     dst[4];     // swizzled dst offsets (same pattern for A and B)
    uint32_t     a_sz[4];    // 16 or 0 (zero-fill padded rows)
};

__device__ __forceinline__ void mm_setup_dst(MMCtx& cx, int tid) {
    int chunk = tid & 7, rb = tid >> 3;
#pragma unroll
    for (int i = 0; i < 4; i++) {
        int row = rb + 32 * i;
        cx.dst[i] = swz((uint32_t)row * 128u + (uint32_t)chunk * 16u);
    }
}
__device__ __forceinline__ void mm_issue(const MMCtx& cx, uint32_t sb, int buf, int c) {
    uint32_t ab = sb + buf * STG, bb = ab + TLB;
#pragma unroll
    for (int i = 0; i < 4; i++) cp16z(ab + cx.dst[i], cx.a_src[i] + c * KC, cx.a_sz[i]);
#pragma unroll
    for (int i = 0; i < 4; i++) cp16(bb + cx.dst[i], cx.b_src[i] + c * KC);
    cp_commit();
}
__device__ __forceinline__ void mm_compute(uint32_t ab, uint32_t bb,
                                           float acc[2][8][4], int lane, int wm, int wn) {
#pragma unroll
    for (int ks = 0; ks < 4; ks++) {
        int k0 = ks * 8;
        uint32_t a[2][4];
#pragma unroll
        for (int mi = 0; mi < 2; mi++) {
            int row = wm * 32 + mi * 16 + (lane & 15);
            uint32_t o = (uint32_t)row * 128u + (uint32_t)(k0 + ((lane & 16) >> 2)) * 4u;
            ldsm4(a[mi], ab + swz(o));
        }
#pragma unroll
        for (int p = 0; p < 4; p++) {
            int rowN = wn * 64 + p * 16 + (lane & 7) + ((lane & 16) >> 1);
            uint32_t o = (uint32_t)rowN * 128u + (uint32_t)(k0 + ((lane & 8) >> 1)) * 4u;
            uint32_t bf[4];
            ldsm4(bf, bb + swz(o));
            mma8(acc[0][2*p],   a[0], bf[0], bf[1]);
            mma8(acc[1][2*p],   a[1], bf[0], bf[1]);
            mma8(acc[0][2*p+1], a[0], bf[2], bf[3]);
            mma8(acc[1][2*p+1], a[1], bf[2], bf[3]);
        }
    }
}
// 3-stage pipeline, one __syncthreads per K-chunk
__device__ __forceinline__ void mm_loop(const MMCtx& cx, uint32_t sb, int K,
                                        float acc[2][8][4], int lane, int wm, int wn) {
    int NCH = K / KC;
    mm_issue(cx, sb, 0, 0);
    mm_issue(cx, sb, 1, 1);
    for (int c = 0; c < NCH; c++) {
        int b = c % NSTG;
        if (c == NCH - 1) cp_wait0(); else cp_wait1();
        __syncthreads();
        if (c + 2 < NCH) mm_issue(cx, sb, (c + 2) % NSTG, c + 2);
        mm_compute(sb + b * STG, sb + b * STG + TLB, acc, lane, wm, wn);
    }
}

// ---------------- small kernels -------------------------------------------------
__global__ void k_zero() { if (threadIdx.x < NE) g_cnt[threadIdx.x] = 0; }

__global__ void k_round(const float* __restrict__ s, float* __restrict__ d, int n4) {
    int i = blockIdx.x * blockDim.x + threadIdx.x;
    if (i < n4) {
        float4 v = ((const float4*)s)[i];
        ((float4*)d)[i] = make_float4(rtf(v.x), rtf(v.y), rtf(v.z), rtf(v.w));
    }
}

__global__ void k_gate(const float* __restrict__ emb, const float* __restrict__ gw)
{
    int t = (blockIdx.x * blockDim.x + threadIdx.x) >> 5;
    int lane = threadIdx.x & 31;
    if (t >= TOK) return;
    const float* row = emb + (size_t)t * DIM;
    float xr[32];
#pragma unroll
    for (int i = 0; i < 32; i++) xr[i] = row[lane + 32 * i];
    float sc[NE];
#pragma unroll
    for (int e = 0; e < NE; e++) {
        const float* g = gw + e * DIM;
        float acc = 0.f;
#pragma unroll
        for (int i = 0; i < 32; i++) acc += xr[i] * g[lane + 32 * i];
#pragma unroll
        for (int o = 16; o > 0; o >>= 1) acc += __shfl_xor_sync(0xffffffffu, acc, o);
        sc[e] = acc;
    }
    if (lane == 0) {
        float m = sc[0];
#pragma unroll
        for (int e = 1; e < NE; e++) m = fmaxf(m, sc[e]);
        float s = 0.f;
#pragma unroll
        for (int e = 0; e < NE; e++) { sc[e] = expf(sc[e] - m); s += sc[e]; }
        float inv = 1.f / s;
        int i0 = 0;
#pragma unroll
        for (int e = 1; e < NE; e++) if (sc[e] > sc[i0]) i0 = e;
        int i1 = (i0 == 0) ? 1 : 0;
#pragma unroll
        for (int e = 0; e < NE; e++) if (e != i0 && sc[e] > sc[i1]) i1 = e;
        int p0 = atomicAdd(&g_cnt[i0], 1);
        g_list[i0 * TOK + p0] = t * 2;
        g_went[t * 2] = sc[i0] * inv;
        int p1 = atomicAdd(&g_cnt[i1], 1);
        g_list[i1 * TOK + p1] = t * 2 + 1;
        g_went[t * 2 + 1] = sc[i1] * inv;
    }
}

// transpose + tf32 round: dst[b][c][r] = rna(src[b][r][c])
__global__ void k_tr(const float* __restrict__ src, float* __restrict__ dst, int R, int C)
{
    __shared__ float t[32][33];
    size_t boff = (size_t)blockIdx.z * R * C;
    int c0 = blockIdx.x * 32, r0 = blockIdx.y * 32;
    int tx = threadIdx.x, ty = threadIdx.y;
#pragma unroll
    for (int i = 0; i < 32; i += 8)
        t[ty + i][tx] = src[boff + (size_t)(r0 + ty + i) * C + c0 + tx];
    __syncthreads();
#pragma unroll
    for (int i = 0; i < 32; i += 8)
        dst[boff + (size_t)(c0 + ty + i) * R + r0 + tx] = rtf(t[tx][ty + i]);
}

// ---------------- dense GEMM (shared expert) ------------------------------------
// EPI 0: C = acc + bias        EPI 1: C = rtf(silu(acc + bias))
template<int EPI>
__global__ void __launch_bounds__(256, 2) k_dense(
    const float* __restrict__ A, int lda,
    const float* __restrict__ Bt, int K,
    const float* __restrict__ bias,
    float* __restrict__ C, int ldc)
{
    extern __shared__ char dsm[];
    char* base = (char*)(((uintptr_t)dsm + 127) & ~(uintptr_t)127);
    uint32_t sb = smem_u32(base);
    int tid = threadIdx.x, lane = tid & 31, w = tid >> 5;
    int wm = w & 3, wn = w >> 2;
    int r0 = blockIdx.y * BMT, c0 = blockIdx.x * BNT;

    MMCtx cx;
    mm_setup_dst(cx, tid);
    {
        int chunk = tid & 7, rb = tid >> 3;
#pragma unroll
        for (int i = 0; i < 4; i++) {
            int row = rb + 32 * i;
            cx.a_src[i] = A + (size_t)(r0 + row) * lda + chunk * 4;
            cx.a_sz[i] = 16;
            cx.b_src[i] = Bt + (size_t)(c0 + row) * K + chunk * 4;
        }
    }
    float acc[2][8][4] = {};
    mm_loop(cx, sb, K, acc, lane, wm, wn);

    int g = lane >> 2, t4 = lane & 3;
#pragma unroll
    for (int mi = 0; mi < 2; mi++)
#pragma unroll
        for (int h = 0; h < 2; h++) {
            int row = r0 + wm * 32 + mi * 16 + g + h * 8;
            float* cp = C + (size_t)row * ldc;
#pragma unroll
            for (int nj = 0; nj < 8; nj++) {
                int col = c0 + wn * 64 + nj * 8 + 2 * t4;
                float v0 = acc[mi][nj][h * 2 + 0] + bias[col];
                float v1 = acc[mi][nj][h * 2 + 1] + bias[col + 1];
                if (EPI == 1) {
                    v0 = rtf(v0 / (1.f + __expf(-v0)));
                    v1 = rtf(v1 / (1.f + __expf(-v1)));
                }
                *(float2*)(cp + col) = make_float2(v0, v1);
            }
        }
}

// ---------------- routed GEMM ----------------------------------------------------
// GM 0: gather token rows (ent>>1) from p0 (e<2) else p1;  GM 1: gather hbuf rows (ent)
// EPI 0: C[ent] = acc + bias   EPI 3: C[ent] = rtf(silu(ubuf[ent]) * (acc + bias))
template<int GM, int EPI>
__global__ void __launch_bounds__(256, 2) k_moe(
    const float* __restrict__ p0, const float* __restrict__ p1,
    const float* __restrict__ Bt_all, int K, int N,
    const float* __restrict__ bias_all,
    float* __restrict__ C, int ldc)
{
    int e = blockIdx.z;
    int cnt = g_cnt[e];
    int r0 = blockIdx.y * BMT;
    if (r0 >= cnt) return;
    int c0 = blockIdx.x * BNT;

    extern __shared__ char dsm[];
    __shared__ int rs[BMT];
    char* base = (char*)(((uintptr_t)dsm + 127) & ~(uintptr_t)127);
    uint32_t sb = smem_u32(base);
    int tid = threadIdx.x, lane = tid & 31, w = tid >> 5;
    int wm = w & 3, wn = w >> 2;

    if (tid < BMT) rs[tid] = (r0 + tid < cnt) ? g_list[e * TOK + r0 + tid] : -1;
    __syncthreads();

    MMCtx cx;
    mm_setup_dst(cx, tid);
    {
        int chunk = tid & 7, rb = tid >> 3;
        const float* abase = (GM == 0) ? ((e < 2) ? p0 : p1) : p0;
#pragma unroll
        for (int i = 0; i < 4; i++) {
            int row = rb + 32 * i;
            int ent = rs[row];
            bool v = (ent >= 0);
            int arow = (GM == 0) ? (ent >> 1) : ent;
            cx.a_src[i] = v ? abase + (size_t)arow * DIM + chunk * 4 : abase;
            cx.a_sz[i] = v ? 16 : 0;
            cx.b_src[i] = Bt_all + ((size_t)e * N + c0 + row) * K + chunk * 4;
        }
    }
    float acc[2][8][4] = {};
    mm_loop(cx, sb, K, acc, lane, wm, wn);

    const float* bias = bias_all + (size_t)e * N;
    int g = lane >> 2, t4 = lane & 3;
#pragma unroll
    for (int mi = 0; mi < 2; mi++)
#pragma unroll
        for (int h = 0; h < 2; h++) {
            int lr = wm * 32 + mi * 16 + g + h * 8;
            int ent = rs[lr];
            if (ent < 0) continue;
            float* cp = C + (size_t)ent * ldc;
            const float* up = g_ubuf + (size_t)ent * HID;
#pragma unroll
            for (int nj = 0; nj < 8; nj++) {
                int col = c0 + wn * 64 + nj * 8 + 2 * t4;
                float v0 = acc[mi][nj][h * 2 + 0] + bias[col];
                float v1 = acc[mi][nj][h * 2 + 1] + bias[col + 1];
                if (EPI == 3) {
                    float2 u = *(const float2*)(up + col);
                    v0 = rtf((u.x / (1.f + __expf(-u.x))) * v0);
                    v1 = rtf((u.y / (1.f + __expf(-u.y))) * v1);
                }
                *(float2*)(cp + col) = make_float2(v0, v1);
            }
        }
}

// ---------------- final combine: out[t] += w0*o[2t] + w1*o[2t+1] ------------------
__global__ void k_comb(float* __restrict__ out) {
    int t = blockIdx.x;
    int d = threadIdx.x * 4;
    float w0 = g_went[t * 2], w1 = g_went[t * 2 + 1];
    float4 a = *(const float4*)(g_ubuf + (size_t)(t * 2) * DIM + d);
    float4 b = *(const float4*)(g_ubuf + (size_t)(t * 2 + 1) * DIM + d);
    float4 z = *(float4*)(out + (size_t)t * DIM + d);
    z.x += w0 * a.x + w1 * b.x;
    z.y += w0 * a.y + w1 * b.y;
    z.z += w0 * a.z + w1 * b.z;
    z.w += w0 * a.w + w1 * b.w;
    *(float4*)(out + (size_t)t * DIM + d) = z;
}

// ---------------- launcher ---------------------------------------------------------
extern "C" void kernel_launch(void* const* d_in, const int* in_sizes, int n_in,
                              void* d_out, int out_size)
{
    const float* emb = (const float*)d_in[0];
    const float* x   = (const float*)d_in[1];
    const float* gw  = (const float*)d_in[2];
    const float* W1  = (const float*)d_in[3];
    const float* B1  = (const float*)d_in[4];
    const float* W2  = (const float*)d_in[5];
    const float* B2  = (const float*)d_in[6];
    const float* W3  = (const float*)d_in[7];
    const float* B3  = (const float*)d_in[8];
    const float* sW1 = (const float*)d_in[9];
    const float* sB1 = (const float*)d_in[10];
    const float* sW2 = (const float*)d_in[11];
    const float* sB2 = (const float*)d_in[12];
    float* out = (float*)d_out;

    cudaFuncSetAttribute(k_dense<0>, cudaFuncAttributeMaxDynamicSharedMemorySize, SMEM_GEMM);
    cudaFuncSetAttribute(k_dense<1>, cudaFuncAttributeMaxDynamicSharedMemorySize, SMEM_GEMM);
    cudaFuncSetAttribute(k_moe<0,0>, cudaFuncAttributeMaxDynamicSharedMemorySize, SMEM_GEMM);
    cudaFuncSetAttribute(k_moe<0,3>, cudaFuncAttributeMaxDynamicSharedMemorySize, SMEM_GEMM);
    cudaFuncSetAttribute(k_moe<1,0>, cudaFuncAttributeMaxDynamicSharedMemorySize, SMEM_GEMM);

    float *embr, *xr, *ubuf, *hbuf, *zbuf, *tw1, *tw3, *tw2, *tsw1, *tsw2;
    cudaGetSymbolAddress((void**)&embr, g_embr);
    cudaGetSymbolAddress((void**)&xr,   g_xr);
    cudaGetSymbolAddress((void**)&ubuf, g_ubuf);
    cudaGetSymbolAddress((void**)&hbuf, g_hbuf);
    cudaGetSymbolAddress((void**)&zbuf, g_zbuf);
    cudaGetSymbolAddress((void**)&tw1,  g_tw1);
    cudaGetSymbolAddress((void**)&tw3,  g_tw3);
    cudaGetSymbolAddress((void**)&tw2,  g_tw2);
    cudaGetSymbolAddress((void**)&tsw1, g_tsw1);
    cudaGetSymbolAddress((void**)&tsw2, g_tsw2);

    k_zero<<<1, 32>>>();
    k_gate<<<TOK / 4, 128>>>(emb, gw);

    int n4a = TOK * DIM / 4;
    k_round<<<(n4a + 255) / 256, 256>>>(emb, embr, n4a);
    k_round<<<(n4a + 255) / 256, 256>>>(x,   xr,   n4a);

    // transpose + round weights (K-major for ldsm B)
    dim3 tb(32, 8);
    k_tr<<<dim3(SHH / 32, DIM / 32, 1),  tb>>>(sW1, tsw1, DIM, SHH);
    k_tr<<<dim3(DIM / 32, SHH / 32, 1),  tb>>>(sW2, tsw2, SHH, DIM);
    k_tr<<<dim3(HID / 32, DIM / 32, NE), tb>>>(W1, tw1, DIM, HID);
    k_tr<<<dim3(HID / 32, DIM / 32, NE), tb>>>(W3, tw3, DIM, HID);
    k_tr<<<dim3(DIM / 32, HID / 32, NE), tb>>>(W2, tw2, HID, DIM);

    // shared expert
    k_dense<1><<<dim3(SHH / BNT, TOK / BMT), 256, SMEM_GEMM>>>(embr, DIM, tsw1, DIM, sB1, zbuf, SHH);
    k_dense<0><<<dim3(DIM / BNT, TOK / BMT), 256, SMEM_GEMM>>>(zbuf, SHH, tsw2, SHH, sB2, out, DIM);

    // routed experts: u = W1 pre-act; h = rtf(silu(u) * (W3 pre-act)); o = h @ W2 + B2
    k_moe<0,0><<<dim3(HID / BNT, TOK / BMT, NE), 256, SMEM_GEMM>>>(xr, embr, tw1, DIM, HID, B1, ubuf, HID);
    k_moe<0,3><<<dim3(HID / BNT, TOK / BMT, NE), 256, SMEM_GEMM>>>(xr, embr, tw3, DIM, HID, B3, hbuf, HID);
    k_moe<1,0><<<dim3(DIM / BNT, TOK / BMT, NE), 256, SMEM_GEMM>>>(hbuf, hbuf, tw2, HID, DIM, B2, ubuf, DIM);
    k_comb<<<TOK, 256>>>(out);

    (void)in_sizes; (void)n_in; (void)out_size;
}